// round 11
// baseline (speedup 1.0000x reference)
#include <cuda_runtime.h>
#include <cstddef>
#include <cstdint>

#define HDIM 64
#define NMAX 100352

// ---------------- scratch (static device globals; no allocation allowed) ----
__device__ float g_aggu[(size_t)NMAX * HDIM];
__device__ float g_aggb[(size_t)NMAX * HDIM];
__device__ float g_y1u[(size_t)NMAX * HDIM];
__device__ float g_y1b[(size_t)NMAX * HDIM];
__device__ float g_y2[(size_t)NMAX * 2 * HDIM];
__device__ float g_stats[5 * 128];     // per BN: [0..63]=sum, [64..127]=sumsq

// ---------------- init: agg = (1+eps)*x, zero stats ------------------------
__global__ void init_kernel(const float* __restrict__ x,
                            const float* __restrict__ eps1,
                            const float* __restrict__ eps2,
                            float* __restrict__ aggu,
                            float* __restrict__ aggb,
                            float* __restrict__ stats,
                            int total4)
{
    int i = blockIdx.x * blockDim.x + threadIdx.x;
    if (i < 5 * 128) stats[i] = 0.0f;
    float a = 1.0f + __ldg(eps1);
    float b = 1.0f + __ldg(eps2);
    const float4* x4 = (const float4*)x;
    float4* u4 = (float4*)aggu;
    float4* b4 = (float4*)aggb;
    int stride = gridDim.x * blockDim.x;
    for (int t = i; t < total4; t += stride) {
        float4 v = x4[t];
        float4 r;
        r.x = a * v.x; r.y = a * v.y; r.z = a * v.z; r.w = a * v.w;
        u4[t] = r;
        float4 s;
        s.x = b * v.x; s.y = b * v.y; s.z = b * v.z; s.w = b * v.w;
        b4[t] = s;
    }
}

// ---------------- merged scatter-add for both edge sets ---------------------
__global__ void scatter2_kernel(const float* __restrict__ featu,
                                const int* __restrict__ du,
                                const int* __restrict__ su, int EU,
                                const float* __restrict__ featb,
                                const int* __restrict__ db,
                                const int* __restrict__ sb, int EB,
                                float* __restrict__ aggu,
                                float* __restrict__ aggb)
{
    long t = blockIdx.x * (long)blockDim.x + threadIdx.x;
    long stride = gridDim.x * (long)blockDim.x;
    long total = (long)(EU + EB) * 16;
    for (long i = t; i < total; i += stride) {
        int e = (int)(i >> 4);
        int c = (int)(i & 15);
        const float* feat;
        float* agg;
        int dst, src;
        if (e < EU) {
            dst = __ldg(&du[e]);
            src = __ldg(&su[e]);
            feat = featu; agg = aggu;
        } else {
            int eb = e - EU;
            dst = __ldg(&db[eb]);
            src = __ldg(&sb[eb]);
            feat = featb; agg = aggb;
        }
        float4 v = *(const float4*)(feat + ((size_t)src << 6) + c * 4);
        float* p = agg + ((size_t)dst << 6) + c * 4;
        asm volatile("red.global.add.v4.f32 [%0], {%1,%2,%3,%4};"
                     :: "l"(p), "f"(v.x), "f"(v.y), "f"(v.z), "f"(v.w)
                     : "memory");
    }
}

// ---------------- f32x2 helpers --------------------------------------------
__device__ __forceinline__ void ffma2(unsigned long long& d,
                                      unsigned long long a,
                                      unsigned long long b) {
    asm("fma.rn.f32x2 %0, %1, %2, %0;" : "+l"(d) : "l"(a), "l"(b));
}
__device__ __forceinline__ float2 unpk(unsigned long long v) {
    unsigned int lo, hi;
    asm("mov.b64 {%0, %1}, %2;" : "=r"(lo), "=r"(hi) : "l"(v));
    return make_float2(__uint_as_float(lo), __uint_as_float(hi));
}

// ---------------- GEMM + bias + fused input BN(from stats)+ReLU + BN stats --
// Y[i][j] = sum_k act(A[i][k]) * W[k][j] + bias[j]
// Row-pair-packed f32x2 accumulators: acc[rp][j] holds (row even, row odd).
// A pairs load pre-packed from transposed As (adjacent rows contiguous);
// W is stored DUPLICATED in smem so (W_j, W_j) pairs load directly.
// Inner loop: 6 LDS.128 + 32 FFMA2 per k-step per thread, zero movs.
// Shared memory > 48KB -> dynamic smem (opt-in attribute).
struct GArg {
    const float* A;
    const float* W;
    const float* bias;
    const float* st0; const float* g0; const float* be0;
    const float* st1; const float* g1; const float* be1;
    float* Y;
    float* stats;
};

#define AST 260                        // As row stride (floats)
#define F_AS   0                       // As: 32 x AST
#define F_WS2  (32 * AST)              // Ws2: 32 x 128
#define F_SC   (F_WS2 + 32 * 128)      // sSc: K floats, then sSh: K floats
static constexpr int SMEM_FLOATS(int K) { return F_SC + 2 * K; }

template <int K, bool AFF>
__global__ __launch_bounds__(256, 2)
void gemm_bn(GArg ga, GArg gb, int ldY, int N, float invN)
{
    extern __shared__ float smf[];
    float (*As)[AST]  = (float(*)[AST])(smf + F_AS);
    float (*Ws2)[128] = (float(*)[128])(smf + F_WS2);
    float* sSc = smf + F_SC;
    float* sSh = sSc + K;

    const GArg g = (blockIdx.y == 0) ? ga : gb;

    const int tid  = threadIdx.x;         // 0..255
    const int lane = tid & 31;
    const int wy   = tid >> 5;            // col group (8 cols), 0..7
    const int rbase = blockIdx.x * 256;

    if (AFF) {
        if (tid < K) {
            const float* st = (tid < 64) ? g.st0 : g.st1;
            const float* gg = (tid < 64) ? g.g0  : g.g1;
            const float* bb = (tid < 64) ? g.be0 : g.be1;
            int j = tid & 63;
            float mean = st[j] * invN;
            float var  = st[64 + j] * invN - mean * mean;
            float s = gg[j] * rsqrtf(var + 1e-5f);
            sSc[tid] = s;
            sSh[tid] = bb[j] - mean * s;
        }
        __syncthreads();
    }

    // acc[rp][j]: rp = row pair (0..3), j = col (0..7).
    // rp 0/1 -> rows lane*4 + {0,1} / {2,3}; rp 2/3 -> rows 128 + lane*4 + {0,1}/{2,3}
    unsigned long long acc[4][8];
#pragma unroll
    for (int i = 0; i < 4; i++)
#pragma unroll
        for (int j = 0; j < 8; j++) acc[i][j] = 0ull;

#pragma unroll
    for (int kc = 0; kc < K; kc += 32) {
        // --- load A chunk (256 rows x 32 cols), transform, transpose-store
#pragma unroll
        for (int it = 0; it < 8; it++) {
            int lin = it * 256 + tid;     // 2048 float4 slots
            int r   = lin >> 3;           // 8 float4 per row
            int c4  = lin & 7;
            int gr  = rbase + r;
            float4 v = make_float4(0.f, 0.f, 0.f, 0.f);
            if (gr < N)
                v = *(const float4*)&g.A[(size_t)gr * K + kc + c4 * 4];
            if (AFF) {
                int c = kc + c4 * 4;
                float4 s = *(const float4*)&sSc[c];
                float4 h = *(const float4*)&sSh[c];
                v.x = fmaxf(v.x * s.x + h.x, 0.f);
                v.y = fmaxf(v.y * s.y + h.y, 0.f);
                v.z = fmaxf(v.z * s.z + h.z, 0.f);
                v.w = fmaxf(v.w * s.w + h.w, 0.f);
            }
            As[c4 * 4 + 0][r] = v.x;
            As[c4 * 4 + 1][r] = v.y;
            As[c4 * 4 + 2][r] = v.z;
            As[c4 * 4 + 3][r] = v.w;
        }
        // --- load W chunk (32 rows x 64 cols), store duplicated pairs
#pragma unroll
        for (int it = 0; it < 4; it++) {
            int lin = it * 256 + tid;     // 1024 float2 slots
            int r   = lin >> 5;           // 32 float2 per row
            int c2  = lin & 31;
            float2 w = *(const float2*)&g.W[(size_t)(kc + r) * 64 + c2 * 2];
            float4 d = make_float4(w.x, w.x, w.y, w.y);
            *(float4*)&Ws2[r][c2 * 4] = d;
        }
        __syncthreads();

        // --- compute: row-pair-packed f32x2, zero movs
#pragma unroll
        for (int k = 0; k < 32; k++) {
            ulonglong2 a01 = *(const ulonglong2*)&As[k][lane * 4];
            ulonglong2 a23 = *(const ulonglong2*)&As[k][128 + lane * 4];
            ulonglong2 b01 = *(const ulonglong2*)&Ws2[k][wy * 16];
            ulonglong2 b23 = *(const ulonglong2*)&Ws2[k][wy * 16 + 4];
            ulonglong2 b45 = *(const ulonglong2*)&Ws2[k][wy * 16 + 8];
            ulonglong2 b67 = *(const ulonglong2*)&Ws2[k][wy * 16 + 12];
            unsigned long long ap[4] = { a01.x, a01.y, a23.x, a23.y };
            unsigned long long bp[8] = { b01.x, b01.y, b23.x, b23.y,
                                         b45.x, b45.y, b67.x, b67.y };
#pragma unroll
            for (int i = 0; i < 4; i++)
#pragma unroll
                for (int j = 0; j < 8; j++)
                    ffma2(acc[i][j], ap[i], bp[j]);
        }
        if (kc + 32 < K) __syncthreads();
    }

    // --- epilogue: bias, store, per-warp stats reduction
    float b[8];
    *(float4*)&b[0] = *(const float4*)&g.bias[wy * 8];
    *(float4*)&b[4] = *(const float4*)&g.bias[wy * 8 + 4];

    float psum[8], psq[8];
#pragma unroll
    for (int j = 0; j < 8; j++) { psum[j] = 0.f; psq[j] = 0.f; }

#pragma unroll
    for (int rp = 0; rp < 4; rp++) {
        int rowe = rbase + ((rp < 2) ? (lane * 4 + rp * 2) : (128 + lane * 4 + (rp - 2) * 2));
        float2 pr[8];
#pragma unroll
        for (int j = 0; j < 8; j++) pr[j] = unpk(acc[rp][j]);
        // even row
        if (rowe < N) {
            float v[8];
#pragma unroll
            for (int j = 0; j < 8; j++) {
                v[j] = pr[j].x + b[j];
                psum[j] += v[j];
                psq[j]  += v[j] * v[j];
            }
            float* yp = &g.Y[(size_t)rowe * ldY + wy * 8];
            *(float4*)&yp[0] = *(float4*)&v[0];
            *(float4*)&yp[4] = *(float4*)&v[4];
        }
        // odd row
        if (rowe + 1 < N) {
            float v[8];
#pragma unroll
            for (int j = 0; j < 8; j++) {
                v[j] = pr[j].y + b[j];
                psum[j] += v[j];
                psq[j]  += v[j] * v[j];
            }
            float* yp = &g.Y[(size_t)(rowe + 1) * ldY + wy * 8];
            *(float4*)&yp[0] = *(float4*)&v[0];
            *(float4*)&yp[4] = *(float4*)&v[4];
        }
    }
    // warp-wide reduce (all lanes participate; OOB rows contributed 0)
#pragma unroll
    for (int j = 0; j < 8; j++) {
#pragma unroll
        for (int o = 16; o > 0; o >>= 1) {
            psum[j] += __shfl_xor_sync(0xFFFFFFFFu, psum[j], o);
            psq[j]  += __shfl_xor_sync(0xFFFFFFFFu, psq[j],  o);
        }
    }
    if (lane == 0) {
#pragma unroll
        for (int j = 0; j < 8; j++) {
            atomicAdd(&g.stats[wy * 8 + j], psum[j]);
            atomicAdd(&g.stats[64 + wy * 8 + j], psq[j]);
        }
    }
}

// ---------------- final BN + ReLU (coeffs in-kernel) ------------------------
__global__ void bnrelu_kernel(float* __restrict__ Y,
                              const float* __restrict__ stats,
                              const float* __restrict__ g,
                              const float* __restrict__ be,
                              int total4, float invN)
{
    __shared__ float sc[64], sh[64];
    if (threadIdx.x < 64) {
        int j = threadIdx.x;
        float mean = stats[j] * invN;
        float var  = stats[64 + j] * invN - mean * mean;
        float s = g[j] * rsqrtf(var + 1e-5f);
        sc[j] = s;
        sh[j] = be[j] - mean * s;
    }
    __syncthreads();
    int i = blockIdx.x * blockDim.x + threadIdx.x;
    int stride = gridDim.x * blockDim.x;
    float4* y4 = (float4*)Y;
    for (int t = i; t < total4; t += stride) {
        int c = (t * 4) & 63;
        float4 v = y4[t];
        float4 s = *(const float4*)&sc[c];
        float4 h = *(const float4*)&sh[c];
        v.x = fmaxf(v.x * s.x + h.x, 0.f);
        v.y = fmaxf(v.y * s.y + h.y, 0.f);
        v.z = fmaxf(v.z * s.z + h.z, 0.f);
        v.w = fmaxf(v.w * s.w + h.w, 0.f);
        y4[t] = v;
    }
}

// ---------------- launch ----------------------------------------------------
extern "C" void kernel_launch(void* const* d_in, const int* in_sizes, int n_in,
                              void* d_out, int out_size)
{
    const float* x     = (const float*)d_in[0];
    const float* battr = (const float*)d_in[1];
    const int*   upidx = (const int*)d_in[2];
    const int*   bidx  = (const int*)d_in[3];
    const float* eps1  = (const float*)d_in[4];
    const float* eps2  = (const float*)d_in[5];
    const float* uw1 = (const float*)d_in[6];
    const float* ub1 = (const float*)d_in[7];
    const float* ug1 = (const float*)d_in[8];
    const float* ube1= (const float*)d_in[9];
    const float* uw2 = (const float*)d_in[10];
    const float* ub2 = (const float*)d_in[11];
    const float* ug2 = (const float*)d_in[12];
    const float* ube2= (const float*)d_in[13];
    const float* bw1 = (const float*)d_in[14];
    const float* bb1 = (const float*)d_in[15];
    const float* bg1 = (const float*)d_in[16];
    const float* bbe1= (const float*)d_in[17];
    const float* bw2 = (const float*)d_in[18];
    const float* bb2 = (const float*)d_in[19];
    const float* bg2 = (const float*)d_in[20];
    const float* bbe2= (const float*)d_in[21];
    const float* cw  = (const float*)d_in[22];
    const float* cb  = (const float*)d_in[23];
    const float* cg  = (const float*)d_in[24];
    const float* cbe = (const float*)d_in[25];
    float* out = (float*)d_out;

    int N  = in_sizes[0] / HDIM;
    int EU = in_sizes[2] / 2;
    int EB = in_sizes[3] / 2;

    float *aggu, *aggb, *y1u, *y1b, *y2, *stats;
    cudaGetSymbolAddress((void**)&aggu,  g_aggu);
    cudaGetSymbolAddress((void**)&aggb,  g_aggb);
    cudaGetSymbolAddress((void**)&y1u,   g_y1u);
    cudaGetSymbolAddress((void**)&y1b,   g_y1b);
    cudaGetSymbolAddress((void**)&y2,    g_y2);
    cudaGetSymbolAddress((void**)&stats, g_stats);

    int smem64  = SMEM_FLOATS(64) * 4;
    int smem128 = SMEM_FLOATS(128) * 4;
    cudaFuncSetAttribute(gemm_bn<64, false>,
                         cudaFuncAttributeMaxDynamicSharedMemorySize, smem64);
    cudaFuncSetAttribute(gemm_bn<64, true>,
                         cudaFuncAttributeMaxDynamicSharedMemorySize, smem64);
    cudaFuncSetAttribute(gemm_bn<128, true>,
                         cudaFuncAttributeMaxDynamicSharedMemorySize, smem128);

    float invN = 1.0f / (float)N;
    int total4 = (N * HDIM) / 4;
    int gb = (N + 255) / 256;

    // Phase 0: init aggregates + zero stats
    init_kernel<<<592, 256>>>(x, eps1, eps2, aggu, aggb, stats, total4);

    // Phase 1: merged scatter-adds (vectorized RED)
    // up:       agg_up[up_index[0][e]]       += x[up_index[1][e]]
    // boundary: agg_b [boundary_index[1][e]] += battr[boundary_index[0][e]]
    scatter2_kernel<<<10240, 256>>>(x, upidx, upidx + EU, EU,
                                    battr, bidx + EB, bidx, EB,
                                    aggu, aggb);

    // Phase 2: layer-1 GEMMs (merged dual launch, fused stats)
    {
        GArg gu = { aggu, uw1, ub1, nullptr, nullptr, nullptr,
                    nullptr, nullptr, nullptr, y1u, stats + 0 };
        GArg gv = { aggb, bw1, bb1, nullptr, nullptr, nullptr,
                    nullptr, nullptr, nullptr, y1b, stats + 128 };
        gemm_bn<64, false><<<dim3(gb, 2), 256, smem64>>>(gu, gv, 64, N, invN);
    }

    // Phase 3: layer-2 GEMMs, input BN+ReLU coeffs computed in-kernel
    {
        GArg gu = { y1u, uw2, ub2, stats + 0,   ug1, ube1,
                    stats + 0,   ug1, ube1, y2,      stats + 256 };
        GArg gv = { y1b, bw2, bb2, stats + 128, bg1, bbe1,
                    stats + 128, bg1, bbe1, y2 + 64, stats + 384 };
        gemm_bn<64, true><<<dim3(gb, 2), 256, smem64>>>(gu, gv, 128, N, invN);
    }

    // Phase 4: combine GEMM (K=128), input BN+ReLU from two stats sets
    {
        GArg gc = { y2, cw, cb, stats + 256, ug2, ube2,
                    stats + 384, bg2, bbe2, out, stats + 512 };
        gemm_bn<128, true><<<dim3(gb, 1), 256, smem128>>>(gc, gc, 64, N, invN);
    }

    // Phase 5: final BN+ReLU in place on out
    bnrelu_kernel<<<592, 256>>>(out, stats + 512, cg, cbe, total4, invN);
}

// round 12
// speedup vs baseline: 1.1148x; 1.1148x over previous
#include <cuda_runtime.h>
#include <cstddef>
#include <cstdint>

#define HDIM 64
#define NMAX 100352

// ---------------- scratch (static device globals; no allocation allowed) ----
__device__ float g_aggu[(size_t)NMAX * HDIM];
__device__ float g_aggb[(size_t)NMAX * HDIM];
__device__ float g_y1u[(size_t)NMAX * HDIM];
__device__ float g_y1b[(size_t)NMAX * HDIM];
__device__ float g_y2[(size_t)NMAX * 2 * HDIM];
__device__ float g_stats[5 * 128];     // per BN: [0..63]=sum, [64..127]=sumsq

// ---------------- init: agg = (1+eps)*x, zero stats ------------------------
__global__ void init_kernel(const float* __restrict__ x,
                            const float* __restrict__ eps1,
                            const float* __restrict__ eps2,
                            float* __restrict__ aggu,
                            float* __restrict__ aggb,
                            float* __restrict__ stats,
                            int total4)
{
    int i = blockIdx.x * blockDim.x + threadIdx.x;
    if (i < 5 * 128) stats[i] = 0.0f;
    float a = 1.0f + __ldg(eps1);
    float b = 1.0f + __ldg(eps2);
    const float4* x4 = (const float4*)x;
    float4* u4 = (float4*)aggu;
    float4* b4 = (float4*)aggb;
    int stride = gridDim.x * blockDim.x;
    for (int t = i; t < total4; t += stride) {
        float4 v = x4[t];
        float4 r;
        r.x = a * v.x; r.y = a * v.y; r.z = a * v.z; r.w = a * v.w;
        u4[t] = r;
        float4 s;
        s.x = b * v.x; s.y = b * v.y; s.z = b * v.z; s.w = b * v.w;
        b4[t] = s;
    }
}

// ---------------- merged scatter-add for both edge sets ---------------------
__global__ void scatter2_kernel(const float* __restrict__ featu,
                                const int* __restrict__ du,
                                const int* __restrict__ su, int EU,
                                const float* __restrict__ featb,
                                const int* __restrict__ db,
                                const int* __restrict__ sb, int EB,
                                float* __restrict__ aggu,
                                float* __restrict__ aggb)
{
    long t = blockIdx.x * (long)blockDim.x + threadIdx.x;
    long stride = gridDim.x * (long)blockDim.x;
    long total = (long)(EU + EB) * 16;
    for (long i = t; i < total; i += stride) {
        int e = (int)(i >> 4);
        int c = (int)(i & 15);
        const float* feat;
        float* agg;
        int dst, src;
        if (e < EU) {
            dst = __ldg(&du[e]);
            src = __ldg(&su[e]);
            feat = featu; agg = aggu;
        } else {
            int eb = e - EU;
            dst = __ldg(&db[eb]);
            src = __ldg(&sb[eb]);
            feat = featb; agg = aggb;
        }
        float4 v = *(const float4*)(feat + ((size_t)src << 6) + c * 4);
        float* p = agg + ((size_t)dst << 6) + c * 4;
        asm volatile("red.global.add.v4.f32 [%0], {%1,%2,%3,%4};"
                     :: "l"(p), "f"(v.x), "f"(v.y), "f"(v.z), "f"(v.w)
                     : "memory");
    }
}

// ---------------- f32x2 helpers --------------------------------------------
__device__ __forceinline__ unsigned long long dup2(float v) {
    unsigned long long r;
    asm("mov.b64 %0, {%1, %1};" : "=l"(r) : "r"(__float_as_uint(v)));
    return r;
}
__device__ __forceinline__ void ffma2(unsigned long long& d,
                                      unsigned long long a,
                                      unsigned long long b) {
    asm("fma.rn.f32x2 %0, %1, %2, %0;" : "+l"(d) : "l"(a), "l"(b));
}
__device__ __forceinline__ float2 unpk(unsigned long long v) {
    unsigned int lo, hi;
    asm("mov.b64 {%0, %1}, %2;" : "=r"(lo), "=r"(hi) : "l"(v));
    return make_float2(__uint_as_float(lo), __uint_as_float(hi));
}

// ---------------- GEMM + bias + fused input BN(from stats)+ReLU + BN stats --
// Y[i][j] = sum_k act(A[i][k]) * W[k][j] + bias[j]
// 2D warp tiling: 8 warps = 4 row-groups x 2 col-groups. Warp = 64 rows x 32
// cols; thread = 8 rows (two contiguous quads) x 8 cols. A row-pairs load
// pre-packed for f32x2 (zero A movs); W duplicated into pairs via movs.
// Each warp's A LDS touches only its own 128B slice -> ~2x fewer L1 wavefronts
// than the lane-wide layout.
struct GArg {
    const float* A;
    const float* W;
    const float* bias;
    const float* st0; const float* g0; const float* be0;
    const float* st1; const float* g1; const float* be1;
    float* Y;
    float* stats;
};

template <int K, bool AFF>
__global__ __launch_bounds__(256, 2)
void gemm_bn(GArg ga, GArg gb, int ldY, int N, float invN)
{
    __shared__ float As[32][260];   // transposed A chunk: As[k][row]
    __shared__ float Ws[32][68];    // W chunk: Ws[k][col]
    __shared__ float SRED[128];
    __shared__ float sSc[AFF ? K : 1];
    __shared__ float sSh[AFF ? K : 1];

    const GArg g = (blockIdx.y == 0) ? ga : gb;

    const int tid  = threadIdx.x;         // 0..255
    const int lane = tid & 31;
    const int wid  = tid >> 5;
    const int wr   = wid >> 1;            // 0..3, 64 rows each
    const int wc   = wid & 1;             // 0..1, 32 cols each
    const int rg   = lane & 7;            // row quad group
    const int cg   = lane >> 3;           // 0..3, 8 cols each
    const int rbase = blockIdx.x * 256;
    const int colb  = wc * 32 + cg * 8;

    if (tid < 128) SRED[tid] = 0.0f;

    if (AFF) {
        if (tid < K) {
            const float* st = (tid < 64) ? g.st0 : g.st1;
            const float* gg = (tid < 64) ? g.g0  : g.g1;
            const float* bb = (tid < 64) ? g.be0 : g.be1;
            int j = tid & 63;
            float mean = st[j] * invN;
            float var  = st[64 + j] * invN - mean * mean;
            float s = gg[j] * rsqrtf(var + 1e-5f);
            sSc[tid] = s;
            sSh[tid] = bb[j] - mean * s;
        }
        __syncthreads();
    }

    // acc[rp][j]: rp<2 -> quad1 rows (r0 + 2rp, +1); rp>=2 -> quad2 (+32)
    unsigned long long acc[4][8];
#pragma unroll
    for (int i = 0; i < 4; i++)
#pragma unroll
        for (int j = 0; j < 8; j++) acc[i][j] = 0ull;

#pragma unroll
    for (int kc = 0; kc < K; kc += 32) {
        // --- load A chunk (256 rows x 32 cols), transform, transpose-store
#pragma unroll
        for (int it = 0; it < 8; it++) {
            int lin = it * 256 + tid;     // 2048 float4 slots
            int r   = lin >> 3;           // 8 float4 per row
            int c4  = lin & 7;
            int gr  = rbase + r;
            float4 v = make_float4(0.f, 0.f, 0.f, 0.f);
            if (gr < N)
                v = *(const float4*)&g.A[(size_t)gr * K + kc + c4 * 4];
            if (AFF) {
                int c = kc + c4 * 4;
                float4 s = *(const float4*)&sSc[c];
                float4 h = *(const float4*)&sSh[c];
                v.x = fmaxf(v.x * s.x + h.x, 0.f);
                v.y = fmaxf(v.y * s.y + h.y, 0.f);
                v.z = fmaxf(v.z * s.z + h.z, 0.f);
                v.w = fmaxf(v.w * s.w + h.w, 0.f);
            }
            As[c4 * 4 + 0][r] = v.x;
            As[c4 * 4 + 1][r] = v.y;
            As[c4 * 4 + 2][r] = v.z;
            As[c4 * 4 + 3][r] = v.w;
        }
        // --- load W chunk (32 rows x 64 cols)
#pragma unroll
        for (int it = 0; it < 2; it++) {
            int lin = it * 256 + tid;     // 512 float4
            int r   = lin >> 4;
            int c4  = lin & 15;
            *(float4*)&Ws[r][c4 * 4] = *(const float4*)&g.W[(size_t)(kc + r) * 64 + c4 * 4];
        }
        __syncthreads();

        // --- compute: 2D warp tile, row-pair-packed f32x2
#pragma unroll
        for (int k = 0; k < 32; k++) {
            ulonglong2 a01 = *(const ulonglong2*)&As[k][wr * 64 + rg * 4];
            ulonglong2 a23 = *(const ulonglong2*)&As[k][wr * 64 + 32 + rg * 4];
            float4 w0 = *(const float4*)&Ws[k][colb];
            float4 w1 = *(const float4*)&Ws[k][colb + 4];
            unsigned long long ap[4] = { a01.x, a01.y, a23.x, a23.y };
            unsigned long long bp[8] = {
                dup2(w0.x), dup2(w0.y), dup2(w0.z), dup2(w0.w),
                dup2(w1.x), dup2(w1.y), dup2(w1.z), dup2(w1.w)
            };
#pragma unroll
            for (int i = 0; i < 4; i++)
#pragma unroll
                for (int j = 0; j < 8; j++)
                    ffma2(acc[i][j], ap[i], bp[j]);
        }
        if (kc + 32 < K) __syncthreads();
    }

    // --- epilogue: bias, store, stats ---------------------------------------
    float b[8];
    *(float4*)&b[0] = *(const float4*)&g.bias[colb];
    *(float4*)&b[4] = *(const float4*)&g.bias[colb + 4];

    float psum[8], psq[8];
#pragma unroll
    for (int j = 0; j < 8; j++) { psum[j] = 0.f; psq[j] = 0.f; }

    const int r0 = rbase + wr * 64 + rg * 4;
#pragma unroll
    for (int rp = 0; rp < 4; rp++) {
        int rowe = (rp < 2) ? (r0 + rp * 2) : (r0 + 32 + (rp - 2) * 2);
        float2 pr[8];
#pragma unroll
        for (int j = 0; j < 8; j++) pr[j] = unpk(acc[rp][j]);
        // even row
        if (rowe < N) {
            float v[8];
#pragma unroll
            for (int j = 0; j < 8; j++) {
                v[j] = pr[j].x + b[j];
                psum[j] += v[j];
                psq[j]  += v[j] * v[j];
            }
            float* yp = &g.Y[(size_t)rowe * ldY + colb];
            *(float4*)&yp[0] = *(float4*)&v[0];
            *(float4*)&yp[4] = *(float4*)&v[4];
        }
        // odd row
        if (rowe + 1 < N) {
            float v[8];
#pragma unroll
            for (int j = 0; j < 8; j++) {
                v[j] = pr[j].y + b[j];
                psum[j] += v[j];
                psq[j]  += v[j] * v[j];
            }
            float* yp = &g.Y[(size_t)(rowe + 1) * ldY + colb];
            *(float4*)&yp[0] = *(float4*)&v[0];
            *(float4*)&yp[4] = *(float4*)&v[4];
        }
    }
    // reduce over rg (lanes sharing the same cg/cols): xor offsets 1,2,4
#pragma unroll
    for (int j = 0; j < 8; j++) {
#pragma unroll
        for (int o = 1; o <= 4; o <<= 1) {
            psum[j] += __shfl_xor_sync(0xFFFFFFFFu, psum[j], o);
            psq[j]  += __shfl_xor_sync(0xFFFFFFFFu, psq[j],  o);
        }
    }
    if (rg == 0) {
#pragma unroll
        for (int j = 0; j < 8; j++) {
            atomicAdd(&SRED[colb + j], psum[j]);
            atomicAdd(&SRED[64 + colb + j], psq[j]);
        }
    }
    __syncthreads();
    if (tid < 128) atomicAdd(&g.stats[tid], SRED[tid]);
}

// ---------------- final BN + ReLU (coeffs in-kernel) ------------------------
__global__ void bnrelu_kernel(float* __restrict__ Y,
                              const float* __restrict__ stats,
                              const float* __restrict__ g,
                              const float* __restrict__ be,
                              int total4, float invN)
{
    __shared__ float sc[64], sh[64];
    if (threadIdx.x < 64) {
        int j = threadIdx.x;
        float mean = stats[j] * invN;
        float var  = stats[64 + j] * invN - mean * mean;
        float s = g[j] * rsqrtf(var + 1e-5f);
        sc[j] = s;
        sh[j] = be[j] - mean * s;
    }
    __syncthreads();
    int i = blockIdx.x * blockDim.x + threadIdx.x;
    int stride = gridDim.x * blockDim.x;
    float4* y4 = (float4*)Y;
    for (int t = i; t < total4; t += stride) {
        int c = (t * 4) & 63;
        float4 v = y4[t];
        float4 s = *(const float4*)&sc[c];
        float4 h = *(const float4*)&sh[c];
        v.x = fmaxf(v.x * s.x + h.x, 0.f);
        v.y = fmaxf(v.y * s.y + h.y, 0.f);
        v.z = fmaxf(v.z * s.z + h.z, 0.f);
        v.w = fmaxf(v.w * s.w + h.w, 0.f);
        y4[t] = v;
    }
}

// ---------------- launch ----------------------------------------------------
extern "C" void kernel_launch(void* const* d_in, const int* in_sizes, int n_in,
                              void* d_out, int out_size)
{
    const float* x     = (const float*)d_in[0];
    const float* battr = (const float*)d_in[1];
    const int*   upidx = (const int*)d_in[2];
    const int*   bidx  = (const int*)d_in[3];
    const float* eps1  = (const float*)d_in[4];
    const float* eps2  = (const float*)d_in[5];
    const float* uw1 = (const float*)d_in[6];
    const float* ub1 = (const float*)d_in[7];
    const float* ug1 = (const float*)d_in[8];
    const float* ube1= (const float*)d_in[9];
    const float* uw2 = (const float*)d_in[10];
    const float* ub2 = (const float*)d_in[11];
    const float* ug2 = (const float*)d_in[12];
    const float* ube2= (const float*)d_in[13];
    const float* bw1 = (const float*)d_in[14];
    const float* bb1 = (const float*)d_in[15];
    const float* bg1 = (const float*)d_in[16];
    const float* bbe1= (const float*)d_in[17];
    const float* bw2 = (const float*)d_in[18];
    const float* bb2 = (const float*)d_in[19];
    const float* bg2 = (const float*)d_in[20];
    const float* bbe2= (const float*)d_in[21];
    const float* cw  = (const float*)d_in[22];
    const float* cb  = (const float*)d_in[23];
    const float* cg  = (const float*)d_in[24];
    const float* cbe = (const float*)d_in[25];
    float* out = (float*)d_out;

    int N  = in_sizes[0] / HDIM;
    int EU = in_sizes[2] / 2;
    int EB = in_sizes[3] / 2;

    float *aggu, *aggb, *y1u, *y1b, *y2, *stats;
    cudaGetSymbolAddress((void**)&aggu,  g_aggu);
    cudaGetSymbolAddress((void**)&aggb,  g_aggb);
    cudaGetSymbolAddress((void**)&y1u,   g_y1u);
    cudaGetSymbolAddress((void**)&y1b,   g_y1b);
    cudaGetSymbolAddress((void**)&y2,    g_y2);
    cudaGetSymbolAddress((void**)&stats, g_stats);

    float invN = 1.0f / (float)N;
    int total4 = (N * HDIM) / 4;
    int gb = (N + 255) / 256;

    // Phase 0: init aggregates + zero stats
    init_kernel<<<592, 256>>>(x, eps1, eps2, aggu, aggb, stats, total4);

    // Phase 1: merged scatter-adds (vectorized RED)
    // up:       agg_up[up_index[0][e]]       += x[up_index[1][e]]
    // boundary: agg_b [boundary_index[1][e]] += battr[boundary_index[0][e]]
    scatter2_kernel<<<10240, 256>>>(x, upidx, upidx + EU, EU,
                                    battr, bidx + EB, bidx, EB,
                                    aggu, aggb);

    // Phase 2: layer-1 GEMMs (merged dual launch, fused stats)
    {
        GArg gu = { aggu, uw1, ub1, nullptr, nullptr, nullptr,
                    nullptr, nullptr, nullptr, y1u, stats + 0 };
        GArg gv = { aggb, bw1, bb1, nullptr, nullptr, nullptr,
                    nullptr, nullptr, nullptr, y1b, stats + 128 };
        gemm_bn<64, false><<<dim3(gb, 2), 256>>>(gu, gv, 64, N, invN);
    }

    // Phase 3: layer-2 GEMMs, input BN+ReLU coeffs computed in-kernel
    {
        GArg gu = { y1u, uw2, ub2, stats + 0,   ug1, ube1,
                    stats + 0,   ug1, ube1, y2,      stats + 256 };
        GArg gv = { y1b, bw2, bb2, stats + 128, bg1, bbe1,
                    stats + 128, bg1, bbe1, y2 + 64, stats + 384 };
        gemm_bn<64, true><<<dim3(gb, 2), 256>>>(gu, gv, 128, N, invN);
    }

    // Phase 4: combine GEMM (K=128), input BN+ReLU from two stats sets
    {
        GArg gc = { y2, cw, cb, stats + 256, ug2, ube2,
                    stats + 384, bg2, bbe2, out, stats + 512 };
        gemm_bn<128, true><<<dim3(gb, 1), 256>>>(gc, gc, 64, N, invN);
    }

    // Phase 5: final BN+ReLU in place on out
    bnrelu_kernel<<<592, 256>>>(out, stats + 512, cg, cbe, total4, invN);
}

// round 15
// speedup vs baseline: 1.1262x; 1.0103x over previous
#include <cuda_runtime.h>
#include <cstddef>
#include <cstdint>

#define HDIM 64
#define NMAX 100352

// ---------------- scratch (static device globals; no allocation allowed) ----
__device__ float g_aggu[(size_t)NMAX * HDIM];
__device__ float g_aggb[(size_t)NMAX * HDIM];
__device__ float g_y1u[(size_t)NMAX * HDIM];
__device__ float g_y1b[(size_t)NMAX * HDIM];
__device__ float g_y2[(size_t)NMAX * 2 * HDIM];
__device__ float g_stats[5 * 128];     // per BN: [0..63]=sum, [64..127]=sumsq

// ---------------- init: agg = (1+eps)*x, zero stats ------------------------
__global__ void init_kernel(const float* __restrict__ x,
                            const float* __restrict__ eps1,
                            const float* __restrict__ eps2,
                            float* __restrict__ aggu,
                            float* __restrict__ aggb,
                            float* __restrict__ stats,
                            int total4)
{
    int i = blockIdx.x * blockDim.x + threadIdx.x;
    if (i < 5 * 128) stats[i] = 0.0f;
    float a = 1.0f + __ldg(eps1);
    float b = 1.0f + __ldg(eps2);
    const float4* x4 = (const float4*)x;
    float4* u4 = (float4*)aggu;
    float4* b4 = (float4*)aggb;
    int stride = gridDim.x * blockDim.x;
    for (int t = i; t < total4; t += stride) {
        float4 v = x4[t];
        float4 r;
        r.x = a * v.x; r.y = a * v.y; r.z = a * v.z; r.w = a * v.w;
        u4[t] = r;
        float4 s;
        s.x = b * v.x; s.y = b * v.y; s.z = b * v.z; s.w = b * v.w;
        b4[t] = s;
    }
}

// ---------------- merged scatter-add for both edge sets ---------------------
__global__ void scatter2_kernel(const float* __restrict__ featu,
                                const int* __restrict__ du,
                                const int* __restrict__ su, int EU,
                                const float* __restrict__ featb,
                                const int* __restrict__ db,
                                const int* __restrict__ sb, int EB,
                                float* __restrict__ aggu,
                                float* __restrict__ aggb)
{
    long t = blockIdx.x * (long)blockDim.x + threadIdx.x;
    long stride = gridDim.x * (long)blockDim.x;
    long total = (long)(EU + EB) * 16;
    for (long i = t; i < total; i += stride) {
        int e = (int)(i >> 4);
        int c = (int)(i & 15);
        const float* feat;
        float* agg;
        int dst, src;
        if (e < EU) {
            dst = __ldg(&du[e]);
            src = __ldg(&su[e]);
            feat = featu; agg = aggu;
        } else {
            int eb = e - EU;
            dst = __ldg(&db[eb]);
            src = __ldg(&sb[eb]);
            feat = featb; agg = aggb;
        }
        float4 v = *(const float4*)(feat + ((size_t)src << 6) + c * 4);
        float* p = agg + ((size_t)dst << 6) + c * 4;
        asm volatile("red.global.add.v4.f32 [%0], {%1,%2,%3,%4};"
                     :: "l"(p), "f"(v.x), "f"(v.y), "f"(v.z), "f"(v.w)
                     : "memory");
    }
}

// ---------------- f32x2 helpers --------------------------------------------
__device__ __forceinline__ unsigned long long dup2(float v) {
    unsigned long long r;
    asm("mov.b64 %0, {%1, %1};" : "=l"(r) : "r"(__float_as_uint(v)));
    return r;
}
__device__ __forceinline__ void ffma2(unsigned long long& d,
                                      unsigned long long a,
                                      unsigned long long b) {
    asm("fma.rn.f32x2 %0, %1, %2, %0;" : "+l"(d) : "l"(a), "l"(b));
}
__device__ __forceinline__ float2 unpk(unsigned long long v) {
    unsigned int lo, hi;
    asm("mov.b64 {%0, %1}, %2;" : "=r"(lo), "=r"(hi) : "l"(v));
    return make_float2(__uint_as_float(lo), __uint_as_float(hi));
}

// ---------------- GEMM + bias + fused input BN(from stats)+ReLU + BN stats --
// Y[i][j] = sum_k act(A[i][k]) * W[k][j] + bias[j]
// 2D warp tiling (4 row-groups x 2 col-groups); thread = 8 rows x 8 cols,
// row-pair-packed f32x2 accumulators.
// As is XOR-bank-swizzled: element (k, r) lives at As[k][r ^ (k_in & 28)].
//   - staging scalar STS becomes conflict-free (bank = 4*c4 + s, all distinct)
//   - compute LDS.128 stays 16B-aligned (swizzle is a multiple of 4 floats)
//     and still covers 32 banks once per load -> 1 wavefront.
struct GArg {
    const float* A;
    const float* W;
    const float* bias;
    const float* st0; const float* g0; const float* be0;
    const float* st1; const float* g1; const float* be1;
    float* Y;
    float* stats;
};

template <int K, bool AFF>
__global__ __launch_bounds__(256, 2)
void gemm_bn(GArg ga, GArg gb, int ldY, int N, float invN)
{
    __shared__ float As[32][256];   // transposed + XOR-swizzled A chunk
    __shared__ float Ws[32][68];    // W chunk: Ws[k][col]
    __shared__ float SRED[128];
    __shared__ float sSc[AFF ? K : 1];
    __shared__ float sSh[AFF ? K : 1];

    const GArg g = (blockIdx.y == 0) ? ga : gb;

    const int tid  = threadIdx.x;         // 0..255
    const int lane = tid & 31;
    const int wid  = tid >> 5;
    const int wr   = wid >> 1;            // 0..3, 64 rows each
    const int wc   = wid & 1;             // 0..1, 32 cols each
    const int rg   = lane & 7;            // row quad group
    const int cg   = lane >> 3;           // 0..3, 8 cols each
    const int rbase = blockIdx.x * 256;
    const int colb  = wc * 32 + cg * 8;

    if (tid < 128) SRED[tid] = 0.0f;

    if (AFF) {
        if (tid < K) {
            const float* st = (tid < 64) ? g.st0 : g.st1;
            const float* gg = (tid < 64) ? g.g0  : g.g1;
            const float* bb = (tid < 64) ? g.be0 : g.be1;
            int j = tid & 63;
            float mean = st[j] * invN;
            float var  = st[64 + j] * invN - mean * mean;
            float s = gg[j] * rsqrtf(var + 1e-5f);
            sSc[tid] = s;
            sSh[tid] = bb[j] - mean * s;
        }
        __syncthreads();
    }

    // acc[rp][j]: rp<2 -> quad1 rows (r0 + 2rp, +1); rp>=2 -> quad2 (+32)
    unsigned long long acc[4][8];
#pragma unroll
    for (int i = 0; i < 4; i++)
#pragma unroll
        for (int j = 0; j < 8; j++) acc[i][j] = 0ull;

#pragma unroll
    for (int kc = 0; kc < K; kc += 32) {
        // --- load A chunk (256 rows x 32 cols), transform, swizzled transpose
#pragma unroll
        for (int it = 0; it < 8; it++) {
            int lin = it * 256 + tid;     // 2048 float4 slots
            int r   = lin >> 3;           // 8 float4 per row
            int c4  = lin & 7;            // column group within chunk
            int gr  = rbase + r;
            float4 v = make_float4(0.f, 0.f, 0.f, 0.f);
            if (gr < N)
                v = *(const float4*)&g.A[(size_t)gr * K + kc + c4 * 4];
            if (AFF) {
                int c = kc + c4 * 4;
                float4 s = *(const float4*)&sSc[c];
                float4 h = *(const float4*)&sSh[c];
                v.x = fmaxf(v.x * s.x + h.x, 0.f);
                v.y = fmaxf(v.y * s.y + h.y, 0.f);
                v.z = fmaxf(v.z * s.z + h.z, 0.f);
                v.w = fmaxf(v.w * s.w + h.w, 0.f);
            }
            int rs = r ^ (c4 * 4);        // XOR swizzle (bits 2-4)
            As[c4 * 4 + 0][rs] = v.x;
            As[c4 * 4 + 1][rs] = v.y;
            As[c4 * 4 + 2][rs] = v.z;
            As[c4 * 4 + 3][rs] = v.w;
        }
        // --- load W chunk (32 rows x 64 cols)
#pragma unroll
        for (int it = 0; it < 2; it++) {
            int lin = it * 256 + tid;     // 512 float4
            int r   = lin >> 4;
            int c4  = lin & 15;
            *(float4*)&Ws[r][c4 * 4] = *(const float4*)&g.W[(size_t)(kc + r) * 64 + c4 * 4];
        }
        __syncthreads();

        // --- compute: 2D warp tile, row-pair-packed f32x2, swizzled A loads
#pragma unroll
        for (int k = 0; k < 32; k++) {
            int swz = k & 28;             // 4*(k/4), bits 2-4
            int ra  = (wr * 64 + rg * 4) ^ swz;
            ulonglong2 a01 = *(const ulonglong2*)&As[k][ra];
            ulonglong2 a23 = *(const ulonglong2*)&As[k][ra + 32];
            float4 w0 = *(const float4*)&Ws[k][colb];
            float4 w1 = *(const float4*)&Ws[k][colb + 4];
            unsigned long long ap[4] = { a01.x, a01.y, a23.x, a23.y };
            unsigned long long bp[8] = {
                dup2(w0.x), dup2(w0.y), dup2(w0.z), dup2(w0.w),
                dup2(w1.x), dup2(w1.y), dup2(w1.z), dup2(w1.w)
            };
#pragma unroll
            for (int i = 0; i < 4; i++)
#pragma unroll
                for (int j = 0; j < 8; j++)
                    ffma2(acc[i][j], ap[i], bp[j]);
        }
        if (kc + 32 < K) __syncthreads();
    }

    // --- epilogue: bias, store, stats ---------------------------------------
    float b[8];
    *(float4*)&b[0] = *(const float4*)&g.bias[colb];
    *(float4*)&b[4] = *(const float4*)&g.bias[colb + 4];

    float psum[8], psq[8];
#pragma unroll
    for (int j = 0; j < 8; j++) { psum[j] = 0.f; psq[j] = 0.f; }

    const int r0 = rbase + wr * 64 + rg * 4;
#pragma unroll
    for (int rp = 0; rp < 4; rp++) {
        int rowe = (rp < 2) ? (r0 + rp * 2) : (r0 + 32 + (rp - 2) * 2);
        float2 pr[8];
#pragma unroll
        for (int j = 0; j < 8; j++) pr[j] = unpk(acc[rp][j]);
        // even row
        if (rowe < N) {
            float v[8];
#pragma unroll
            for (int j = 0; j < 8; j++) {
                v[j] = pr[j].x + b[j];
                psum[j] += v[j];
                psq[j]  += v[j] * v[j];
            }
            float* yp = &g.Y[(size_t)rowe * ldY + colb];
            *(float4*)&yp[0] = *(float4*)&v[0];
            *(float4*)&yp[4] = *(float4*)&v[4];
        }
        // odd row
        if (rowe + 1 < N) {
            float v[8];
#pragma unroll
            for (int j = 0; j < 8; j++) {
                v[j] = pr[j].y + b[j];
                psum[j] += v[j];
                psq[j]  += v[j] * v[j];
            }
            float* yp = &g.Y[(size_t)(rowe + 1) * ldY + colb];
            *(float4*)&yp[0] = *(float4*)&v[0];
            *(float4*)&yp[4] = *(float4*)&v[4];
        }
    }
    // reduce over rg (lanes sharing the same cg/cols): xor offsets 1,2,4
#pragma unroll
    for (int j = 0; j < 8; j++) {
#pragma unroll
        for (int o = 1; o <= 4; o <<= 1) {
            psum[j] += __shfl_xor_sync(0xFFFFFFFFu, psum[j], o);
            psq[j]  += __shfl_xor_sync(0xFFFFFFFFu, psq[j],  o);
        }
    }
    if (rg == 0) {
#pragma unroll
        for (int j = 0; j < 8; j++) {
            atomicAdd(&SRED[colb + j], psum[j]);
            atomicAdd(&SRED[64 + colb + j], psq[j]);
        }
    }
    __syncthreads();
    if (tid < 128) atomicAdd(&g.stats[tid], SRED[tid]);
}

// ---------------- final BN + ReLU (coeffs in-kernel) ------------------------
__global__ void bnrelu_kernel(float* __restrict__ Y,
                              const float* __restrict__ stats,
                              const float* __restrict__ g,
                              const float* __restrict__ be,
                              int total4, float invN)
{
    __shared__ float sc[64], sh[64];
    if (threadIdx.x < 64) {
        int j = threadIdx.x;
        float mean = stats[j] * invN;
        float var  = stats[64 + j] * invN - mean * mean;
        float s = g[j] * rsqrtf(var + 1e-5f);
        sc[j] = s;
        sh[j] = be[j] - mean * s;
    }
    __syncthreads();
    int i = blockIdx.x * blockDim.x + threadIdx.x;
    int stride = gridDim.x * blockDim.x;
    float4* y4 = (float4*)Y;
    for (int t = i; t < total4; t += stride) {
        int c = (t * 4) & 63;
        float4 v = y4[t];
        float4 s = *(const float4*)&sc[c];
        float4 h = *(const float4*)&sh[c];
        v.x = fmaxf(v.x * s.x + h.x, 0.f);
        v.y = fmaxf(v.y * s.y + h.y, 0.f);
        v.z = fmaxf(v.z * s.z + h.z, 0.f);
        v.w = fmaxf(v.w * s.w + h.w, 0.f);
        y4[t] = v;
    }
}

// ---------------- launch ----------------------------------------------------
extern "C" void kernel_launch(void* const* d_in, const int* in_sizes, int n_in,
                              void* d_out, int out_size)
{
    const float* x     = (const float*)d_in[0];
    const float* battr = (const float*)d_in[1];
    const int*   upidx = (const int*)d_in[2];
    const int*   bidx  = (const int*)d_in[3];
    const float* eps1  = (const float*)d_in[4];
    const float* eps2  = (const float*)d_in[5];
    const float* uw1 = (const float*)d_in[6];
    const float* ub1 = (const float*)d_in[7];
    const float* ug1 = (const float*)d_in[8];
    const float* ube1= (const float*)d_in[9];
    const float* uw2 = (const float*)d_in[10];
    const float* ub2 = (const float*)d_in[11];
    const float* ug2 = (const float*)d_in[12];
    const float* ube2= (const float*)d_in[13];
    const float* bw1 = (const float*)d_in[14];
    const float* bb1 = (const float*)d_in[15];
    const float* bg1 = (const float*)d_in[16];
    const float* bbe1= (const float*)d_in[17];
    const float* bw2 = (const float*)d_in[18];
    const float* bb2 = (const float*)d_in[19];
    const float* bg2 = (const float*)d_in[20];
    const float* bbe2= (const float*)d_in[21];
    const float* cw  = (const float*)d_in[22];
    const float* cb  = (const float*)d_in[23];
    const float* cg  = (const float*)d_in[24];
    const float* cbe = (const float*)d_in[25];
    float* out = (float*)d_out;

    int N  = in_sizes[0] / HDIM;
    int EU = in_sizes[2] / 2;
    int EB = in_sizes[3] / 2;

    float *aggu, *aggb, *y1u, *y1b, *y2, *stats;
    cudaGetSymbolAddress((void**)&aggu,  g_aggu);
    cudaGetSymbolAddress((void**)&aggb,  g_aggb);
    cudaGetSymbolAddress((void**)&y1u,   g_y1u);
    cudaGetSymbolAddress((void**)&y1b,   g_y1b);
    cudaGetSymbolAddress((void**)&y2,    g_y2);
    cudaGetSymbolAddress((void**)&stats, g_stats);

    float invN = 1.0f / (float)N;
    int total4 = (N * HDIM) / 4;
    int gb = (N + 255) / 256;

    // Phase 0: init aggregates + zero stats
    init_kernel<<<592, 256>>>(x, eps1, eps2, aggu, aggb, stats, total4);

    // Phase 1: merged scatter-adds (vectorized RED)
    // up:       agg_up[up_index[0][e]]       += x[up_index[1][e]]
    // boundary: agg_b [boundary_index[1][e]] += battr[boundary_index[0][e]]
    scatter2_kernel<<<10240, 256>>>(x, upidx, upidx + EU, EU,
                                    battr, bidx + EB, bidx, EB,
                                    aggu, aggb);

    // Phase 2: layer-1 GEMMs (merged dual launch, fused stats)
    {
        GArg gu = { aggu, uw1, ub1, nullptr, nullptr, nullptr,
                    nullptr, nullptr, nullptr, y1u, stats + 0 };
        GArg gv = { aggb, bw1, bb1, nullptr, nullptr, nullptr,
                    nullptr, nullptr, nullptr, y1b, stats + 128 };
        gemm_bn<64, false><<<dim3(gb, 2), 256>>>(gu, gv, 64, N, invN);
    }

    // Phase 3: layer-2 GEMMs, input BN+ReLU coeffs computed in-kernel
    {
        GArg gu = { y1u, uw2, ub2, stats + 0,   ug1, ube1,
                    stats + 0,   ug1, ube1, y2,      stats + 256 };
        GArg gv = { y1b, bw2, bb2, stats + 128, bg1, bbe1,
                    stats + 128, bg1, bbe1, y2 + 64, stats + 384 };
        gemm_bn<64, true><<<dim3(gb, 2), 256>>>(gu, gv, 128, N, invN);
    }

    // Phase 4: combine GEMM (K=128), input BN+ReLU from two stats sets
    {
        GArg gc = { y2, cw, cb, stats + 256, ug2, ube2,
                    stats + 384, bg2, bbe2, out, stats + 512 };
        gemm_bn<128, true><<<dim3(gb, 1), 256>>>(gc, gc, 64, N, invN);
    }

    // Phase 5: final BN+ReLU in place on out
    bnrelu_kernel<<<592, 256>>>(out, stats + 512, cg, cbe, total4, invN);
}